// round 1
// baseline (speedup 1.0000x reference)
#include <cuda_runtime.h>
#include <cstdint>

#define BATCH   8
#define GH      64
#define C0      64
#define NPTS    16384
#define NFREQ   10
#define HID     256
#define P       64
#define SROW    260
#define KC      16
#define K0PAD   240

// ---------------- device scratch (static, allocation-free) ----------------
__device__ float g_gamma[BATCH * HID];
__device__ float g_beta [BATCH * HID];
__device__ float g_W0p  [K0PAD * HID];
__device__ float g_lvl1 [BATCH * 32 * 32 * C0];
__device__ float g_lvl2 [BATCH * 16 * 16 * C0];

// ---------------- helpers ----------------
__device__ __forceinline__ float gelu_f(float x) {
    float x3 = x * x * x;
    float t  = tanhf(0.7978845608028654f * (x + 0.044715f * x3));
    return 0.5f * x * (1.0f + t);
}

__device__ __forceinline__ unsigned long long dup_f32x2(float a) {
    unsigned long long r;
    asm("mov.b64 %0, {%1, %1};" : "=l"(r) : "f"(a));
    return r;
}

__device__ __forceinline__ void fma_f32x2(unsigned long long& d,
                                          unsigned long long a,
                                          unsigned long long b) {
    asm("fma.rn.f32x2 %0, %1, %2, %0;" : "+l"(d) : "l"(a), "l"(b));
}

__device__ __forceinline__ void cp16(uint32_t saddr, const float* g) {
    asm volatile("cp.async.cg.shared.global [%0], [%1], 16;" :: "r"(saddr), "l"(g));
}

// ---------------- prep: FiLM params ----------------
__global__ void prep_ctx_kernel(const float* __restrict__ cv,
                                const float* __restrict__ Wc,
                                const float* __restrict__ bc) {
    int b = blockIdx.x, c = threadIdx.x;
    float g  = bc[c];
    float bt = bc[HID + c];
#pragma unroll 8
    for (int k = 0; k < C0; k++) {
        float v = cv[b * C0 + k];
        g  += v * Wc[k * 2 * HID + c];
        bt += v * Wc[k * 2 * HID + HID + c];
    }
    g_gamma[b * HID + c] = g + 1.0f;
    g_beta [b * HID + c] = bt;
}

// ---------------- prep: pad W0 (234 rows) -> 240 rows, with a 2-row gap
// inserted at row 42 so that feature columns start 16B-aligned in smem.
__global__ void prep_w0_kernel(const float* __restrict__ W0) {
    int r = blockIdx.x, c = threadIdx.x;
    float v = 0.0f;
    if (r < 42)                  v = W0[r * HID + c];
    else if (r >= 44 && r < 236) v = W0[(r - 2) * HID + c];
    g_W0p[r * HID + c] = v;
}

// ---------------- prep: antialiased bilinear pyramid (jax.image.resize) ----
template <int HL>
__global__ void resize_kernel(const float* __restrict__ src) {
    int idx = blockIdx.x * blockDim.x + threadIdx.x;
    int c = idx & (C0 - 1);
    int v = idx >> 6;
    int x = v % HL;
    int y = (v / HL) % HL;
    int b = v / (HL * HL);

    const float scale = (float)(GH / HL);   // 2 or 4
    const int   T     = 2 * (GH / HL);      // taps per dim

    float sy = (y + 0.5f) * scale - 0.5f;
    float sx = (x + 0.5f) * scale - 0.5f;
    int s0y = (int)floorf(sy - scale) + 1;  // ceil(sy - scale)
    int s0x = (int)floorf(sx - scale) + 1;

    float wy[8], wx[8];
    float sumy = 0.f, sumx = 0.f;
#pragma unroll
    for (int t = 0; t < T; t++) {
        int s = s0y + t;
        float w = 1.0f - fabsf((float)s - sy) / scale;
        w = (s >= 0 && s < GH && w > 0.f) ? w : 0.f;
        wy[t] = w; sumy += w;
        s = s0x + t;
        w = 1.0f - fabsf((float)s - sx) / scale;
        w = (s >= 0 && s < GH && w > 0.f) ? w : 0.f;
        wx[t] = w; sumx += w;
    }
    float inv = 1.0f / (sumy * sumx);

    float acc = 0.f;
#pragma unroll
    for (int a = 0; a < T; a++) {
        if (wy[a] == 0.f) continue;
        const float* row = src + ((((b * GH) + (s0y + a)) * GH) << 6) + c;
        float pacc = 0.f;
#pragma unroll
        for (int t = 0; t < T; t++) {
            if (wx[t] == 0.f) continue;
            pacc += wx[t] * row[(s0x + t) << 6];
        }
        acc += wy[a] * pacc;
    }
    float* dst = (HL == 32) ? g_lvl1 : g_lvl2;
    dst[idx] = acc * inv;
}

// ---------------- main fused decoder ----------------
__global__ __launch_bounds__(256, 2)
void decoder_kernel(const float* __restrict__ fg,
                    const float* __restrict__ coords,
                    const float* __restrict__ b0,
                    const float* __restrict__ W1, const float* __restrict__ b1,
                    const float* __restrict__ W2, const float* __restrict__ b2,
                    const float* __restrict__ W3, const float* __restrict__ b3,
                    const float* __restrict__ Wout, const float* __restrict__ bout,
                    float* __restrict__ out) {
    extern __shared__ float smem[];
    float* h_s  = smem;                   // P * SROW   (h tile, [point][col])
    float* w_s  = h_s + P * SROW;         // 2 * KC * HID (weight double buffer)
    float* wo_s = w_s + 2 * KC * HID;     // 3 * HID    (Wout)
    float* bo_s = wo_s + 3 * HID;         // 4          (bout)

    const int tid = threadIdx.x;
    const int b   = blockIdx.x >> 8;
    const int n0  = (blockIdx.x & 255) * P;

    // stage Wout / bout
    for (int i = tid; i < 3 * HID; i += 256) wo_s[i] = Wout[i];
    if (tid < 3) bo_s[tid] = bout[tid];

    // ---- build h tile: posenc + 3-level bilinear samples ----
    {
        int p = tid >> 2, q = tid & 3;
        float cy = coords[(n0 + p) * 2 + 0];
        float cx = coords[(n0 + p) * 2 + 1];

        if (q == 0) {
            float* hp = h_s + p * SROW;
            hp[0] = cy; hp[1] = cx;
            float fr = 3.14159265358979323846f;
#pragma unroll
            for (int f = 0; f < NFREQ; f++) {
                float sv, cvv;
                sincosf(cy * fr, &sv, &cvv);
                hp[2 + 4 * f + 0] = sv;
                hp[2 + 4 * f + 2] = cvv;
                sincosf(cx * fr, &sv, &cvv);
                hp[2 + 4 * f + 1] = sv;
                hp[2 + 4 * f + 3] = cvv;
                fr *= 2.0f;
            }
            // zero padded columns (gap at 42..43, tail 236..239)
            hp[42] = 0.f; hp[43] = 0.f;
            hp[236] = 0.f; hp[237] = 0.f; hp[238] = 0.f; hp[239] = 0.f;
        }

#pragma unroll
        for (int lvl = 0; lvl < 3; lvl++) {
            int Hl = GH >> lvl;
            const float* G = (lvl == 0) ? fg : ((lvl == 1) ? g_lvl1 : g_lvl2);
            float yf = (cy + 1.0f) * 0.5f * (float)(Hl - 1);
            float xf = (cx + 1.0f) * 0.5f * (float)(Hl - 1);
            float y0f = floorf(yf), x0f = floorf(xf);
            float wy = yf - y0f, wx = xf - x0f;
            int y0 = min(max((int)y0f, 0), Hl - 1);
            int x0 = min(max((int)x0f, 0), Hl - 1);
            int y1 = min(y0 + 1, Hl - 1);
            int x1 = min(x0 + 1, Hl - 1);
            const float* p00 = G + ((((b * Hl) + y0) * Hl + x0) << 6);
            const float* p01 = G + ((((b * Hl) + y0) * Hl + x1) << 6);
            const float* p10 = G + ((((b * Hl) + y1) * Hl + x0) << 6);
            const float* p11 = G + ((((b * Hl) + y1) * Hl + x1) << 6);
            float omx = 1.0f - wx, omy = 1.0f - wy;
            float* dst = h_s + p * SROW + 44 + lvl * 64 + q * 16;
#pragma unroll
            for (int cc = 0; cc < 4; cc++) {
                int c = q * 16 + cc * 4;
                float4 v00 = *(const float4*)(p00 + c);
                float4 v01 = *(const float4*)(p01 + c);
                float4 v10 = *(const float4*)(p10 + c);
                float4 v11 = *(const float4*)(p11 + c);
                float4 r;
                r.x = (v00.x * omx + v01.x * wx) * omy + (v10.x * omx + v11.x * wx) * wy;
                r.y = (v00.y * omx + v01.y * wx) * omy + (v10.y * omx + v11.y * wx) * wy;
                r.z = (v00.z * omx + v01.z * wx) * omy + (v10.z * omx + v11.z * wx) * wy;
                r.w = (v00.w * omx + v01.w * wx) * omy + (v10.w * omx + v11.w * wx) * wy;
                *(float4*)(dst + cc * 4) = r;
            }
        }
    }
    __syncthreads();

    // ---- 4 FiLM'd MLP layers, chunked SGEMM with f32x2 FMAs ----
    const int tx = tid & 31, ty = tid >> 5;
    const int cb = tx * 8;
    const float* Wptrs[4] = {g_W0p, W1, W2, W3};
    const float* bptrs[4] = {b0, b1, b2, b3};
    const float* gam = g_gamma + b * HID;
    const float* bet = g_beta  + b * HID;

    for (int l = 0; l < 4; l++) {
        const float* Wl = Wptrs[l];
        const int NCH = (l == 0) ? (K0PAD / KC) : (HID / KC);

        unsigned long long acc[8][4];
#pragma unroll
        for (int i = 0; i < 8; i++)
#pragma unroll
            for (int j = 0; j < 4; j++) acc[i][j] = 0ull;

        // prefetch chunk 0
        {
            const float* gsrc = Wl;
            uint32_t sb = (uint32_t)__cvta_generic_to_shared(w_s);
#pragma unroll
            for (int s = 0; s < 4; s++) {
                int f = tid + s * 256;
                cp16(sb + f * 16, gsrc + f * 4);
            }
            asm volatile("cp.async.commit_group;");
        }

        for (int ch = 0; ch < NCH; ch++) {
            if (ch + 1 < NCH) {
                const float* gsrc = Wl + (ch + 1) * (KC * HID);
                uint32_t sb = (uint32_t)__cvta_generic_to_shared(
                    w_s + ((ch + 1) & 1) * (KC * HID));
#pragma unroll
                for (int s = 0; s < 4; s++) {
                    int f = tid + s * 256;
                    cp16(sb + f * 16, gsrc + f * 4);
                }
                asm volatile("cp.async.commit_group;");
                asm volatile("cp.async.wait_group 1;");
            } else {
                asm volatile("cp.async.wait_group 0;");
            }
            __syncthreads();

            const float* wb = w_s + (ch & 1) * (KC * HID);
            const int kg0 = ch * KC;
#pragma unroll
            for (int kk = 0; kk < KC; kk += 2) {
                float2 a2[8];
#pragma unroll
                for (int i = 0; i < 8; i++)
                    a2[i] = *(const float2*)&h_s[(ty * 8 + i) * SROW + kg0 + kk];
#pragma unroll
                for (int u = 0; u < 2; u++) {
                    const float* wr = wb + (kk + u) * HID + cb;
                    ulonglong2 bA = *(const ulonglong2*)wr;
                    ulonglong2 bB = *(const ulonglong2*)(wr + 4);
                    unsigned long long bp0 = bA.x, bp1 = bA.y, bp2 = bB.x, bp3 = bB.y;
#pragma unroll
                    for (int i = 0; i < 8; i++) {
                        float av = (u == 0) ? a2[i].x : a2[i].y;
                        unsigned long long ad = dup_f32x2(av);
                        fma_f32x2(acc[i][0], ad, bp0);
                        fma_f32x2(acc[i][1], ad, bp1);
                        fma_f32x2(acc[i][2], ad, bp2);
                        fma_f32x2(acc[i][3], ad, bp3);
                    }
                }
            }
            __syncthreads();   // protect w_s buffer before it is re-filled
        }

        // activation: bias + FiLM + gelu, write back transposed-in-place
        float bias[8], ga[8], be[8];
        *(float4*)&bias[0] = *(const float4*)(bptrs[l] + cb);
        *(float4*)&bias[4] = *(const float4*)(bptrs[l] + cb + 4);
        *(float4*)&ga[0]   = *(const float4*)(gam + cb);
        *(float4*)&ga[4]   = *(const float4*)(gam + cb + 4);
        *(float4*)&be[0]   = *(const float4*)(bet + cb);
        *(float4*)&be[4]   = *(const float4*)(bet + cb + 4);

#pragma unroll
        for (int i = 0; i < 8; i++) {
            float o[8];
#pragma unroll
            for (int j4 = 0; j4 < 4; j4++) {
                float lo, hi;
                asm("mov.b64 {%0, %1}, %2;" : "=f"(lo), "=f"(hi) : "l"(acc[i][j4]));
                o[2 * j4] = lo; o[2 * j4 + 1] = hi;
            }
#pragma unroll
            for (int j = 0; j < 8; j++) {
                float v = (o[j] + bias[j]) * ga[j] + be[j];
                o[j] = gelu_f(v);
            }
            float* dst = h_s + (ty * 8 + i) * SROW + cb;
            *(float4*)dst       = make_float4(o[0], o[1], o[2], o[3]);
            *(float4*)(dst + 4) = make_float4(o[4], o[5], o[6], o[7]);
        }
        __syncthreads();
    }

    // ---- output head: tanh(h @ Wout + bout) ----
    if (tid < 192) {
        int p = tid & 63, o = tid >> 6;
        float acc = bo_s[o];
        const float* hp = h_s + p * SROW;
#pragma unroll 8
        for (int k = 0; k < HID; k++) acc += hp[k] * wo_s[k * 3 + o];
        out[((size_t)b * NPTS + n0 + p) * 3 + o] = tanhf(acc);
    }
}

// ---------------- launch ----------------
extern "C" void kernel_launch(void* const* d_in, const int* in_sizes, int n_in,
                              void* d_out, int out_size) {
    const float* fg = (const float*)d_in[0];
    const float* cv = (const float*)d_in[1];
    const float* co = (const float*)d_in[2];
    const float* Wc = (const float*)d_in[3];
    const float* bc = (const float*)d_in[4];
    const float* W0 = (const float*)d_in[5];
    const float* b0 = (const float*)d_in[6];
    const float* W1 = (const float*)d_in[7];
    const float* b1 = (const float*)d_in[8];
    const float* W2 = (const float*)d_in[9];
    const float* b2 = (const float*)d_in[10];
    const float* W3 = (const float*)d_in[11];
    const float* b3 = (const float*)d_in[12];
    const float* Wo = (const float*)d_in[13];
    const float* bo = (const float*)d_in[14];
    float* out = (float*)d_out;

    const int smemB = (P * SROW + 2 * KC * HID + 3 * HID + 4) * 4;
    cudaFuncSetAttribute(decoder_kernel,
                         cudaFuncAttributeMaxDynamicSharedMemorySize, smemB);

    prep_ctx_kernel<<<BATCH, HID>>>(cv, Wc, bc);
    prep_w0_kernel<<<K0PAD, HID>>>(W0);
    resize_kernel<32><<<(BATCH * 32 * 32 * C0) / 256, 256>>>(fg);
    resize_kernel<16><<<(BATCH * 16 * 16 * C0) / 256, 256>>>(fg);
    decoder_kernel<<<BATCH * (NPTS / P), 256, smemB>>>(
        fg, co, b0, W1, b1, W2, b2, W3, b3, Wo, bo, out);
}